// round 7
// baseline (speedup 1.0000x reference)
#include <cuda_runtime.h>
#include <cuda_bf16.h>
#include <cstdint>

// ============================================================================
// spectralNNDeepshared2 — Round 6:
//   - FUSED MLP chain kernel: layer0 + 3 hidden + final in one launch.
//     Activations stay in SMEM (hi/lo bf16); weights stream via cp.async.
//     Final layer writes the out-GEMM B operand directly.
//   - out-GEMM: register-slimmed inner loop (B frags loaded per-pair) so
//     2 CTAs/SM fits without spills. 3-stage cp.async ring.
// ============================================================================

// ---------------- scratch ----------------
__device__ __nv_bfloat16 g_uThi[64 * 1024];
__device__ __nv_bfloat16 g_uTlo[64 * 1024];
__device__ __nv_bfloat16 g_W0hi[64 * 256 * 64];
__device__ __nv_bfloat16 g_W0lo[64 * 256 * 64];
__device__ __nv_bfloat16 g_Whi[3L * 64 * 256 * 256];
__device__ __nv_bfloat16 g_Wlo[3L * 64 * 256 * 256];
__device__ __nv_bfloat16 g_Wfhi[64 * 65 * 256];
__device__ __nv_bfloat16 g_Wflo[64 * 65 * 256];
__device__ __nv_bfloat16 g_Ahi[4096L * 4160];
__device__ __nv_bfloat16 g_Alo[4096L * 4160];
__device__ __nv_bfloat16 g_Bhi[4160L * 1024];
__device__ __nv_bfloat16 g_Blo[4160L * 1024];

__device__ __forceinline__ float sigmoidf_fast(float x) {
    return 1.0f / (1.0f + __expf(-x));
}
__device__ __forceinline__ uint32_t smem_u32(const void* p) {
    uint32_t a;
    asm("{ .reg .u64 t; cvta.to.shared.u64 t, %1; cvt.u32.u64 %0, t; }"
        : "=r"(a) : "l"(p));
    return a;
}

// ---------------- cp.async / ldmatrix / mma helpers ----------------
__device__ __forceinline__ void cp16(uint32_t dst, const void* src) {
    asm volatile("cp.async.cg.shared.global [%0], [%1], 16;\n"
                 :: "r"(dst), "l"(src));
}
__device__ __forceinline__ void cp16z(uint32_t dst, const void* src, bool valid) {
    int sz = valid ? 16 : 0;
    asm volatile("cp.async.cg.shared.global [%0], [%1], 16, %2;\n"
                 :: "r"(dst), "l"(src), "r"(sz));
}
#define CP_COMMIT() asm volatile("cp.async.commit_group;\n" ::: "memory")
#define CP_WAIT(n)  asm volatile("cp.async.wait_group %0;\n" :: "n"(n) : "memory")

__device__ __forceinline__ void ldsm_x4(uint32_t* r, uint32_t addr) {
    asm volatile("ldmatrix.sync.aligned.m8n8.x4.shared.b16 {%0,%1,%2,%3}, [%4];"
        : "=r"(r[0]), "=r"(r[1]), "=r"(r[2]), "=r"(r[3]) : "r"(addr));
}
__device__ __forceinline__ void ldsm_x4t(uint32_t* r, uint32_t addr) {
    asm volatile("ldmatrix.sync.aligned.m8n8.x4.trans.shared.b16 {%0,%1,%2,%3}, [%4];"
        : "=r"(r[0]), "=r"(r[1]), "=r"(r[2]), "=r"(r[3]) : "r"(addr));
}
__device__ __forceinline__ void mma_bf16(float* d, const uint32_t* a, const uint32_t* b) {
    asm volatile(
        "mma.sync.aligned.m16n8k16.row.col.f32.bf16.bf16.f32 "
        "{%0,%1,%2,%3}, {%4,%5,%6,%7}, {%8,%9}, {%0,%1,%2,%3};"
        : "+f"(d[0]), "+f"(d[1]), "+f"(d[2]), "+f"(d[3])
        : "r"(a[0]), "r"(a[1]), "r"(a[2]), "r"(a[3]), "r"(b[0]), "r"(b[1]));
}

// ============================================================================
// Precompute kernels
// ============================================================================
__global__ void split_kernel(const float* __restrict__ src,
                             __nv_bfloat16* __restrict__ hi,
                             __nv_bfloat16* __restrict__ lo, long count)
{
    long i = (long)blockIdx.x * 1024 + threadIdx.x * 4;
    if (i + 3 >= count) {
        for (long k = i; k < count; k++) {
            float v = src[k];
            __nv_bfloat16 h = __float2bfloat16(v);
            hi[k] = h;
            lo[k] = __float2bfloat16(v - __bfloat162float(h));
        }
        return;
    }
    float4 v4 = *reinterpret_cast<const float4*>(src + i);
    float vs[4] = {v4.x, v4.y, v4.z, v4.w};
    __nv_bfloat16 h4[4], l4[4];
    #pragma unroll
    for (int j = 0; j < 4; j++) {
        h4[j] = __float2bfloat16(vs[j]);
        l4[j] = __float2bfloat16(vs[j] - __bfloat162float(h4[j]));
    }
    *reinterpret_cast<uint2*>(hi + i) = *reinterpret_cast<uint2*>(h4);
    *reinterpret_cast<uint2*>(lo + i) = *reinterpret_cast<uint2*>(l4);
}

__global__ void transpose_u_split_kernel(const float* __restrict__ u,
                                         __nv_bfloat16* __restrict__ hi,
                                         __nv_bfloat16* __restrict__ lo)
{
    __shared__ float t[32][33];
    int b0 = blockIdx.x * 32;
    int d0 = blockIdx.y * 32;
    int x = threadIdx.x, y = threadIdx.y;
    t[y][x] = u[(long)(b0 + y) * 64 + (d0 + x)];
    __syncthreads();
    float v = t[x][y];
    __nv_bfloat16 h = __float2bfloat16(v);
    hi[(long)(d0 + y) * 1024 + (b0 + x)] = h;
    lo[(long)(d0 + y) * 1024 + (b0 + x)] = __float2bfloat16(v - __bfloat162float(h));
}

__global__ void build_A_kernel(const float* __restrict__ xi,
                               __nv_bfloat16* __restrict__ Ahi,
                               __nv_bfloat16* __restrict__ Alo)
{
    int n = blockIdx.x;
    for (int k = threadIdx.x; k < 4160; k += 256) {
        int m = k / 65;
        int j = k - m * 65;
        float v = xi[m * 4160 + n + j];
        __nv_bfloat16 h = __float2bfloat16(v);
        float lo = v - __bfloat162float(h);
        Ahi[(long)n * 4160 + k] = h;
        Alo[(long)n * 4160 + k] = __float2bfloat16(lo);
    }
}

// ============================================================================
// FUSED MLP chain kernel
//   grid (8 colblocks, 64 m), 512 threads (16 warps), <=128 regs.
//   SMEM: X (activations, 256 x 128, hi/lo, padded stride) + 2-stage W ring.
//   Column independence: each CTA runs all 5 layers for its 128 batch cols.
// ============================================================================
#define XSTRIDE 272
#define WSTRIDE 80
#define X_HI 0
#define X_LO (256 * XSTRIDE)            // 69632
#define W_BASE (2 * 256 * XSTRIDE)      // 139264
#define W_HI_OFF 0
#define W_LO_OFF 20480
#define WSTAGE 40960
#define FUSED_SMEM (W_BASE + 2 * WSTAGE)  // 221184

__global__ __launch_bounds__(512) void mlp_fused_kernel(
    const __nv_bfloat16* __restrict__ W0h, const __nv_bfloat16* __restrict__ W0l,
    const __nv_bfloat16* __restrict__ Wh,  const __nv_bfloat16* __restrict__ Wl,
    const __nv_bfloat16* __restrict__ Wfh, const __nv_bfloat16* __restrict__ Wfl,
    const float* __restrict__ bias0, const float* __restrict__ biasH,
    const float* __restrict__ biasF,
    const __nv_bfloat16* __restrict__ uTh, const __nv_bfloat16* __restrict__ uTl,
    __nv_bfloat16* __restrict__ Gh, __nv_bfloat16* __restrict__ Gl)
{
    extern __shared__ char smem[];
    const uint32_t sb = smem_u32(smem);
    const int tid = threadIdx.x;
    const int lane = tid & 31;
    const int wid = tid >> 5;
    const int m = blockIdx.y;
    const int c0 = blockIdx.x * 128;

    const int quad = lane >> 3;
    const int r8 = lane & 7;
    const int wr = wid * 16;
    const uint32_t aoff = (wr + (quad & 1) * 8 + r8) * WSTRIDE + (quad >> 1) * 16;
    const uint32_t boff = ((quad & 1) * 8 + r8) * XSTRIDE + (quad >> 1) * 16;
    const int grp = lane >> 2;
    const int qid = lane & 3;

    // ---- load X0 = uT rows 0..63, cols c0..c0+127 ----
    #pragma unroll
    for (int i = 0; i < 2; i++) {
        int idx = tid + i * 512;         // 1024: 64 rows x 16 chunks
        int r = idx >> 4, c = idx & 15;
        long g = (long)r * 1024 + c0 + c * 8;
        uint32_t d = r * XSTRIDE + c * 16;
        cp16(sb + X_HI + d, uTh + g);
        cp16(sb + X_LO + d, uTl + g);
    }
    CP_COMMIT();
    CP_WAIT(0);
    __syncthreads();

    float acc[16][4];

    // ---- one layer: acc = W @ X (split precision) ----
    auto run_layer = [&](const __nv_bfloat16* LWh, const __nv_bfloat16* LWl,
                         int K, int rows) {
        #pragma unroll
        for (int nj = 0; nj < 16; nj++)
            #pragma unroll
            for (int q = 0; q < 4; q++) acc[nj][q] = 0.0f;

        const int nChunks = K >> 5;
        auto loadW = [&](int st, int k0) {
            uint32_t base = sb + W_BASE + (uint32_t)st * WSTAGE;
            #pragma unroll
            for (int i = 0; i < 2; i++) {
                int idx = tid + i * 512;   // 1024: 256 rows x 4 chunks
                int r = idx >> 2, c = idx & 3;
                bool ok = r < rows;
                long g = (long)(ok ? r : 0) * K + k0 + c * 8;
                uint32_t d = r * WSTRIDE + c * 16;
                cp16z(base + W_HI_OFF + d, LWh + g, ok);
                cp16z(base + W_LO_OFF + d, LWl + g, ok);
            }
        };

        loadW(0, 0);
        CP_COMMIT();

        for (int t = 0; t < nChunks; t++) {
            if (t + 1 < nChunks) {
                loadW((t + 1) & 1, (t + 1) * 32);
                CP_COMMIT();
                CP_WAIT(1);
            } else {
                CP_WAIT(0);
            }
            __syncthreads();

            if (wr < rows) {
                uint32_t wbase = sb + W_BASE + (uint32_t)(t & 1) * WSTAGE;
                #pragma unroll
                for (int ks = 0; ks < 2; ks++) {
                    uint32_t ah[4], al[4];
                    ldsm_x4(ah, wbase + W_HI_OFF + aoff + ks * 32);
                    ldsm_x4(al, wbase + W_LO_OFF + aoff + ks * 32);
                    uint32_t xrow = (uint32_t)(t * 32 + ks * 16) * XSTRIDE;
                    #pragma unroll
                    for (int g = 0; g < 8; g++) {
                        uint32_t rh[4], rl[4];
                        ldsm_x4t(rh, sb + X_HI + boff + xrow + g * 32);
                        ldsm_x4t(rl, sb + X_LO + boff + xrow + g * 32);
                        mma_bf16(acc[2 * g],     ah, &rh[0]);
                        mma_bf16(acc[2 * g + 1], ah, &rh[2]);
                        mma_bf16(acc[2 * g],     ah, &rl[0]);
                        mma_bf16(acc[2 * g + 1], ah, &rl[2]);
                        mma_bf16(acc[2 * g],     al, &rh[0]);
                        mma_bf16(acc[2 * g + 1], al, &rh[2]);
                    }
                }
            }
            __syncthreads();
        }
    };

    // ---- epilogue into X smem (hidden layers) ----
    auto store_acts = [&](const float* bias) {
        #pragma unroll
        for (int half = 0; half < 2; half++) {
            int r = wr + grp + half * 8;
            float bv = bias[r];
            #pragma unroll
            for (int nj = 0; nj < 16; nj++) {
                float y0 = sigmoidf_fast(acc[nj][2 * half + 0] + bv);
                float y1 = sigmoidf_fast(acc[nj][2 * half + 1] + bv);
                __nv_bfloat16 h0 = __float2bfloat16(y0);
                __nv_bfloat16 h1 = __float2bfloat16(y1);
                __nv_bfloat16 l0 = __float2bfloat16(y0 - __bfloat162float(h0));
                __nv_bfloat16 l1 = __float2bfloat16(y1 - __bfloat162float(h1));
                __nv_bfloat162 hp; hp.x = h0; hp.y = h1;
                __nv_bfloat162 lp; lp.x = l0; lp.y = l1;
                uint32_t cb = (nj * 8 + qid * 2) * 2;
                *reinterpret_cast<__nv_bfloat162*>(smem + X_HI + r * XSTRIDE + cb) = hp;
                *reinterpret_cast<__nv_bfloat162*>(smem + X_LO + r * XSTRIDE + cb) = lp;
            }
        }
        __syncthreads();
    };

    // layer 0 (K=64) + hidden layers (K=256)
    run_layer(W0h + (long)m * 16384, W0l + (long)m * 16384, 64, 256);
    store_acts(bias0 + m * 256);
    for (int i = 0; i < 3; i++) {
        run_layer(Wh + (long)(i * 64 + m) * 65536, Wl + (long)(i * 64 + m) * 65536,
                  256, 256);
        store_acts(biasH + (i * 64 + m) * 256);
    }

    // final layer (rows=65) -> G global (hi/lo)
    run_layer(Wfh + (long)m * 16640, Wfl + (long)m * 16640, 256, 65);
    {
        const float* bias = biasF + m * 65;
        #pragma unroll
        for (int half = 0; half < 2; half++) {
            int r = wr + grp + half * 8;
            if (r >= 65) continue;
            float bv = bias[r];
            long grow = (long)(m * 65 + r) * 1024 + c0;
            #pragma unroll
            for (int nj = 0; nj < 16; nj++) {
                float y0 = sigmoidf_fast(acc[nj][2 * half + 0] + bv);
                float y1 = sigmoidf_fast(acc[nj][2 * half + 1] + bv);
                __nv_bfloat16 h0 = __float2bfloat16(y0);
                __nv_bfloat16 h1 = __float2bfloat16(y1);
                __nv_bfloat16 l0 = __float2bfloat16(y0 - __bfloat162float(h0));
                __nv_bfloat16 l1 = __float2bfloat16(y1 - __bfloat162float(h1));
                __nv_bfloat162 hp; hp.x = h0; hp.y = h1;
                __nv_bfloat162 lp; lp.x = l0; lp.y = l1;
                int cn = nj * 8 + qid * 2;
                *reinterpret_cast<__nv_bfloat162*>(Gh + grow + cn) = hp;
                *reinterpret_cast<__nv_bfloat162*>(Gl + grow + cn) = lp;
            }
        }
    }
}

// ============================================================================
// Output GEMM: out (4096 x 1024) = A (4096 x 4160) @ B (4160 x 1024)
// Register-slim inner loop (B frags per-pair); 3-stage ring; 2 CTAs/SM.
// ============================================================================
#define ASTRIDE 80
#define BSTRIDE 272
#define A_TILE  (128 * ASTRIDE)
#define B_TILE  (32 * BSTRIDE)
#define STAGE   (2 * A_TILE + 2 * B_TILE)    // 37888 B
#define NSTAGES 3
#define OUT_SMEM_TOTAL (NSTAGES * STAGE)     // 113664 B
#define OFF_AH  0
#define OFF_AL  A_TILE
#define OFF_BH  (2 * A_TILE)
#define OFF_BL  (2 * A_TILE + B_TILE)

__global__ __launch_bounds__(256, 2) void out_mma_kernel(
    const __nv_bfloat16* __restrict__ Ahi, const __nv_bfloat16* __restrict__ Alo,
    const __nv_bfloat16* __restrict__ Bhi, const __nv_bfloat16* __restrict__ Blo,
    float* __restrict__ out)
{
    extern __shared__ char smem[];
    const uint32_t sb = smem_u32(smem);
    const int tid = threadIdx.x;
    const int lane = tid & 31;
    const int wid = tid >> 5;
    const int wm = wid & 3;
    const int wn = wid >> 2;
    const int n0 = blockIdx.y * 128;
    const int col0 = blockIdx.x * 128;

    float acc[2][8][4];
    #pragma unroll
    for (int mi = 0; mi < 2; mi++)
        #pragma unroll
        for (int nj = 0; nj < 8; nj++)
            #pragma unroll
            for (int q = 0; q < 4; q++) acc[mi][nj][q] = 0.0f;

    const int quad = lane >> 3;
    const int r8 = lane & 7;
    const uint32_t aoff = (wm * 32 + (quad & 1) * 8 + r8) * ASTRIDE + (quad >> 1) * 16;
    const uint32_t boff = ((quad & 1) * 8 + r8) * BSTRIDE + (wn * 64 + (quad >> 1) * 8) * 2;

    auto load = [&](int stageIdx, int k0) {
        uint32_t sbase = sb + (uint32_t)stageIdx * STAGE;
        #pragma unroll
        for (int i = 0; i < 2; i++) {
            int idx = tid + i * 256;
            int r = idx >> 2;
            int c = idx & 3;
            long g = (long)(n0 + r) * 4160 + k0 + c * 8;
            uint32_t d = r * ASTRIDE + c * 16;
            cp16(sbase + OFF_AH + d, Ahi + g);
            cp16(sbase + OFF_AL + d, Alo + g);
        }
        #pragma unroll
        for (int i = 0; i < 2; i++) {
            int idx = tid + i * 256;
            int r = idx >> 4;
            int c = idx & 15;
            long g = (long)(k0 + r) * 1024 + col0 + c * 8;
            uint32_t d = r * BSTRIDE + c * 16;
            cp16(sbase + OFF_BH + d, Bhi + g);
            cp16(sbase + OFF_BL + d, Blo + g);
        }
    };

    load(0, 0);
    CP_COMMIT();
    load(1, 32);
    CP_COMMIT();

    int curStage = 0, nxtStage = 2;
    for (int t = 0; t < 130; t++) {
        CP_WAIT(1);
        __syncthreads();
        if (t + 2 < 130) load(nxtStage, (t + 2) * 32);
        CP_COMMIT();

        const uint32_t cur = sb + (uint32_t)curStage * STAGE;
        curStage = (curStage == NSTAGES - 1) ? 0 : curStage + 1;
        nxtStage = (nxtStage == NSTAGES - 1) ? 0 : nxtStage + 1;

        #pragma unroll
        for (int ks = 0; ks < 2; ks++) {
            uint32_t ah[2][4], al[2][4];
            ldsm_x4(ah[0], cur + OFF_AH + aoff + ks * 32);
            ldsm_x4(ah[1], cur + OFF_AH + aoff + 16 * ASTRIDE + ks * 32);
            ldsm_x4(al[0], cur + OFF_AL + aoff + ks * 32);
            ldsm_x4(al[1], cur + OFF_AL + aoff + 16 * ASTRIDE + ks * 32);

            #pragma unroll
            for (int g = 0; g < 4; g++) {
                uint32_t rh[4], rl[4];
                ldsm_x4t(rh, cur + OFF_BH + boff + g * 32 + ks * 16 * BSTRIDE);
                ldsm_x4t(rl, cur + OFF_BL + boff + g * 32 + ks * 16 * BSTRIDE);
                mma_bf16(acc[0][2 * g],     ah[0], &rh[0]);
                mma_bf16(acc[0][2 * g + 1], ah[0], &rh[2]);
                mma_bf16(acc[1][2 * g],     ah[1], &rh[0]);
                mma_bf16(acc[1][2 * g + 1], ah[1], &rh[2]);
                mma_bf16(acc[0][2 * g],     ah[0], &rl[0]);
                mma_bf16(acc[0][2 * g + 1], ah[0], &rl[2]);
                mma_bf16(acc[1][2 * g],     ah[1], &rl[0]);
                mma_bf16(acc[1][2 * g + 1], ah[1], &rl[2]);
                mma_bf16(acc[0][2 * g],     al[0], &rh[0]);
                mma_bf16(acc[0][2 * g + 1], al[0], &rh[2]);
                mma_bf16(acc[1][2 * g],     al[1], &rh[0]);
                mma_bf16(acc[1][2 * g + 1], al[1], &rh[2]);
            }
        }
        __syncthreads();
    }

    const int grp = lane >> 2;
    const int qid = lane & 3;
    #pragma unroll
    for (int mi = 0; mi < 2; mi++) {
        int rbase = n0 + wm * 32 + mi * 16;
        #pragma unroll
        for (int nj = 0; nj < 8; nj++) {
            int cn = col0 + wn * 64 + nj * 8 + qid * 2;
            *reinterpret_cast<float2*>(&out[(long)(rbase + grp) * 1024 + cn]) =
                make_float2(acc[mi][nj][0], acc[mi][nj][1]);
            *reinterpret_cast<float2*>(&out[(long)(rbase + grp + 8) * 1024 + cn]) =
                make_float2(acc[mi][nj][2], acc[mi][nj][3]);
        }
    }
}

// ============================================================================
// Launch
// ============================================================================
extern "C" void kernel_launch(void* const* d_in, const int* in_sizes, int n_in,
                              void* d_out, int out_size) {
    const float* u  = (const float*)d_in[0];
    const float* w0 = (const float*)d_in[1];
    const float* b0 = (const float*)d_in[2];
    const float* w  = (const float*)d_in[3];
    const float* b  = (const float*)d_in[4];
    const float* wf = (const float*)d_in[5];
    const float* bf = (const float*)d_in[6];
    const float* xi = (const float*)d_in[7];
    float* out = (float*)d_out;

    void* p;
    cudaGetSymbolAddress(&p, g_uThi);  __nv_bfloat16* uThi = (__nv_bfloat16*)p;
    cudaGetSymbolAddress(&p, g_uTlo);  __nv_bfloat16* uTlo = (__nv_bfloat16*)p;
    cudaGetSymbolAddress(&p, g_W0hi);  __nv_bfloat16* W0hi = (__nv_bfloat16*)p;
    cudaGetSymbolAddress(&p, g_W0lo);  __nv_bfloat16* W0lo = (__nv_bfloat16*)p;
    cudaGetSymbolAddress(&p, g_Whi);   __nv_bfloat16* Whi  = (__nv_bfloat16*)p;
    cudaGetSymbolAddress(&p, g_Wlo);   __nv_bfloat16* Wlo  = (__nv_bfloat16*)p;
    cudaGetSymbolAddress(&p, g_Wfhi);  __nv_bfloat16* Wfhi = (__nv_bfloat16*)p;
    cudaGetSymbolAddress(&p, g_Wflo);  __nv_bfloat16* Wflo = (__nv_bfloat16*)p;
    cudaGetSymbolAddress(&p, g_Ahi);   __nv_bfloat16* Ahi = (__nv_bfloat16*)p;
    cudaGetSymbolAddress(&p, g_Alo);   __nv_bfloat16* Alo = (__nv_bfloat16*)p;
    cudaGetSymbolAddress(&p, g_Bhi);   __nv_bfloat16* Bhi = (__nv_bfloat16*)p;
    cudaGetSymbolAddress(&p, g_Blo);   __nv_bfloat16* Blo = (__nv_bfloat16*)p;

    cudaFuncSetAttribute(mlp_fused_kernel,
                         cudaFuncAttributeMaxDynamicSharedMemorySize, FUSED_SMEM);
    cudaFuncSetAttribute(out_mma_kernel,
                         cudaFuncAttributeMaxDynamicSharedMemorySize, OUT_SMEM_TOTAL);

    // ---- precompute ----
    build_A_kernel<<<4096, 256>>>(xi, Ahi, Alo);
    {
        long c0 = 64L * 256 * 64;
        split_kernel<<<(unsigned)((c0 + 1023) / 1024), 256>>>(w0, W0hi, W0lo, c0);
        long c1 = 3L * 64 * 256 * 256;
        split_kernel<<<(unsigned)((c1 + 1023) / 1024), 256>>>(w, Whi, Wlo, c1);
        long c2 = 64L * 65 * 256;
        split_kernel<<<(unsigned)((c2 + 1023) / 1024), 256>>>(wf, Wfhi, Wflo, c2);
    }
    transpose_u_split_kernel<<<dim3(32, 2), dim3(32, 32)>>>(u, uThi, uTlo);

    // ---- fused MLP chain (writes G = out-GEMM B operand) ----
    mlp_fused_kernel<<<dim3(8, 64), 512, FUSED_SMEM>>>(
        W0hi, W0lo, Whi, Wlo, Wfhi, Wflo,
        b0, b, bf, uThi, uTlo, Bhi, Blo);

    // ---- output GEMM ----
    out_mma_kernel<<<dim3(8, 32), 256, OUT_SMEM_TOTAL>>>(Ahi, Alo, Bhi, Blo, out);
}